// round 3
// baseline (speedup 1.0000x reference)
#include <cuda_runtime.h>
#include <math.h>

#define RANK 16
#define NF 32

typedef unsigned long long ull;

// ---- shared memory layout (float offsets) ----
#define OFF_W1P 0              // 32i x 4sp x 64 (lane-pair-major) = 8192
#define OFF_W2P 8192           // same layout                       = 8192
#define OFF_W3T 16384          // 256k x 33 (k-major, padded)       = 8448
#define OFF_Y0  24832          // 32 ch x 516 (512 + pad4)          = 16512
#define OFF_Y1  41344          // 8 q2 x 32 ch x 8 sub              = 2048
#define OFF_Y2  43392          // 32 ch x 8                         = 256
#define OFF_RED 43648          // 8 warps x 32                      = 256
#define OFF_W0D 43904          // 32 f x 8 s x 2 (duplicated)       = 512
#define OFF_B0D 44416          // 32 x 2 (duplicated)               = 64
#define OFF_B1  44480
#define OFF_B2  44512
#define OFF_B3  44544
#define OFF_FCW 44576
#define OFF_A   44608
#define OFF_B   44624
#define OFF_C   44640
#define SMEM_FLOATS 44656      // ~178.6 KB -> 1 CTA/SM

__device__ __forceinline__ ull pk2(float lo, float hi) {
    ull r; asm("mov.b64 %0,{%1,%2};" : "=l"(r) : "f"(lo), "f"(hi)); return r;
}
__device__ __forceinline__ void upk2(ull v, float& lo, float& hi) {
    asm("mov.b64 {%0,%1},%2;" : "=f"(lo), "=f"(hi) : "l"(v));
}
__device__ __forceinline__ ull fma2(ull a, ull b, ull c) {
    ull d; asm("fma.rn.f32x2 %0,%1,%2,%3;" : "=l"(d) : "l"(a), "l"(b), "l"(c)); return d;
}
__device__ __forceinline__ ull add2(ull a, ull b) {
    ull d; asm("add.rn.f32x2 %0,%1,%2;" : "=l"(d) : "l"(a), "l"(b)); return d;
}

extern "C" __global__ void __launch_bounds__(256, 1)
ntc_fused_kernel(const int* __restrict__ gi, const int* __restrict__ gj,
                 const int* __restrict__ gk,
                 const float* __restrict__ gA, const float* __restrict__ gB,
                 const float* __restrict__ gC,
                 const float* __restrict__ gW0, const float* __restrict__ gb0,
                 const float* __restrict__ gW1, const float* __restrict__ gb1,
                 const float* __restrict__ gW2, const float* __restrict__ gb2,
                 const float* __restrict__ gW3, const float* __restrict__ gb3,
                 const float* __restrict__ gfcw, const float* __restrict__ gfcb,
                 float* __restrict__ out, int batch, int gridSize)
{
    extern __shared__ float sm[];
    const int tid  = threadIdx.x;
    const int lane = tid & 31;
    const int wq   = tid >> 5;    // warp id 0..7

    // ---- one-time per-CTA weight staging ----
    for (int idx = tid; idx < NF * NF * 8; idx += 256) {
        int o = idx >> 8;          // out channel
        int k = idx & 255;         // i*8 + sub
        int pp = (k >> 1) * 64 + o * 2 + (k & 1);   // pair-major slot
        sm[OFF_W1P + pp] = gW1[idx];
        sm[OFF_W2P + pp] = gW2[idx];
        sm[OFF_W3T + k * 33 + o] = gW3[idx];
    }
    if (tid < 256) {               // W0 duplicated {w,w}
        float w = gW0[tid];
        sm[OFF_W0D + tid * 2]     = w;
        sm[OFF_W0D + tid * 2 + 1] = w;
    }
    if (tid < 64) sm[OFF_B0D + tid] = gb0[tid >> 1];
    if (tid < 32) {
        sm[OFF_B1 + tid]  = gb1[tid];
        sm[OFF_B2 + tid]  = gb2[tid];
        sm[OFF_B3 + tid]  = gb3[tid];
        sm[OFF_FCW + tid] = gfcw[tid];
    }
    const float fc_b = gfcb[0];
    __syncthreads();

    // conv0 per-thread geometry: tid = q0*8 + s0
    const int s0 = tid & 7;
    const int q0 = tid >> 3;

    // conv1 warp->position block map: warp wq owns the 8 conv1 positions whose
    // conv2 block index q2 == wq; sub-position s2 == p.
    int xoff[8];
    {
        int a = (wq >> 2) & 1, b = (wq >> 1) & 1, c = wq & 1;
        #pragma unroll
        for (int p = 0; p < 8; p++) {
            int q1 = (2 * a + (p >> 2)) * 16
                   + (2 * b + ((p >> 1) & 1)) * 4
                   + (2 * c + (p & 1));
            xoff[p] = q1 * 8;
        }
    }

    for (int sample = blockIdx.x; sample < batch; sample += gridSize) {
        // ---- gather a, b, c rows ----
        if (tid < 48) {
            int which = tid >> 4, t = tid & 15;
            if (which == 0)       sm[OFF_A + t] = gA[gi[sample] * RANK + t];
            else if (which == 1)  sm[OFF_B + t] = gB[gj[sample] * RANK + t];
            else                  sm[OFF_C + t] = gC[gk[sample] * RANK + t];
        }
        __syncthreads();

        // ---- conv0: rank-1 input; packed across the two half-positions ----
        ull abp[8];
        {
            float abc0[8], abc1[8];
            #pragma unroll
            for (int half = 0; half < 2; half++) {
                int q = q0 + half * 32;
                int d = 2 * (q >> 4)       + (s0 >> 2);
                int h = 2 * ((q >> 2) & 3) + ((s0 >> 1) & 1);
                int w = 2 * (q & 3)        + (s0 & 1);
                float a0 = sm[OFF_A + 2 * d], a1 = sm[OFF_A + 2 * d + 1];
                float b0 = sm[OFF_B + 2 * h], b1 = sm[OFF_B + 2 * h + 1];
                float c0 = sm[OFF_C + 2 * w], c1 = sm[OFF_C + 2 * w + 1];
                float* t = half ? abc1 : abc0;
                float a0b0 = a0 * b0, a0b1 = a0 * b1;
                float a1b0 = a1 * b0, a1b1 = a1 * b1;
                t[0] = a0b0 * c0; t[1] = a0b0 * c1;
                t[2] = a0b1 * c0; t[3] = a0b1 * c1;
                t[4] = a1b0 * c0; t[5] = a1b0 * c1;
                t[6] = a1b1 * c0; t[7] = a1b1 * c1;
            }
            #pragma unroll
            for (int t = 0; t < 8; t++) abp[t] = pk2(abc0[t], abc1[t]);
        }
        #pragma unroll 4
        for (int f = 0; f < NF; f++) {
            const ulonglong2* wf = (const ulonglong2*)&sm[OFF_W0D + f * 16];
            ulonglong2 Wa = wf[0], Wb = wf[1], Wc = wf[2], Wd = wf[3];
            ull v = *(const ull*)&sm[OFF_B0D + f * 2];
            v = fma2(Wa.x, abp[0], v); v = fma2(Wa.y, abp[1], v);
            v = fma2(Wb.x, abp[2], v); v = fma2(Wb.y, abp[3], v);
            v = fma2(Wc.x, abp[4], v); v = fma2(Wc.y, abp[5], v);
            v = fma2(Wd.x, abp[6], v); v = fma2(Wd.y, abp[7], v);
            float lo, hi; upk2(v, lo, hi);
            sm[OFF_Y0 + f * 516 + tid]       = fmaxf(lo, 0.0f);
            sm[OFF_Y0 + f * 516 + 256 + tid] = fmaxf(hi, 0.0f);
        }
        __syncthreads();

        // ---- conv1 (dominant GEMM, packed f32x2): lane=o, p=sub-position ----
        {
            ull acc[8] = {0,0,0,0,0,0,0,0};
            #pragma unroll 4
            for (int i = 0; i < NF; i++) {
                const float* wrow = &sm[OFF_W1P + i * 256 + lane * 2];
                ull w0 = *(const ull*)(wrow);
                ull w1 = *(const ull*)(wrow + 64);
                ull w2 = *(const ull*)(wrow + 128);
                ull w3 = *(const ull*)(wrow + 192);
                const float* xi = &sm[OFF_Y0 + i * 516];
                #pragma unroll
                for (int p = 0; p < 8; p++) {
                    const ulonglong2* xp = (const ulonglong2*)(xi + xoff[p]);
                    ulonglong2 X0 = xp[0], X1 = xp[1];    // broadcast LDS.128
                    acc[p] = fma2(w0, X0.x, acc[p]);
                    acc[p] = fma2(w1, X0.y, acc[p]);
                    acc[p] = fma2(w2, X1.x, acc[p]);
                    acc[p] = fma2(w3, X1.y, acc[p]);
                }
            }
            float b1v = sm[OFF_B1 + lane];
            float r[8];
            #pragma unroll
            for (int p = 0; p < 8; p++) {
                float lo, hi; upk2(acc[p], lo, hi);
                r[p] = fmaxf(lo + hi + b1v, 0.0f);
            }
            float4* dst = (float4*)&sm[OFF_Y1 + wq * 256 + lane * 8];
            dst[0] = make_float4(r[0], r[1], r[2], r[3]);   // STS.128 x2
            dst[1] = make_float4(r[4], r[5], r[6], r[7]);
        }
        __syncthreads();

        // ---- conv2 (packed): warp = output position wq, lane = o ----
        {
            ull a2[4] = {0,0,0,0};
            #pragma unroll 4
            for (int i = 0; i < NF; i++) {
                const ulonglong2* xq = (const ulonglong2*)&sm[OFF_Y1 + wq * 256 + i * 8];
                ulonglong2 X0 = xq[0], X1 = xq[1];        // broadcast
                const float* wrow = &sm[OFF_W2P + i * 256 + lane * 2];
                a2[0] = fma2(*(const ull*)(wrow),       X0.x, a2[0]);
                a2[1] = fma2(*(const ull*)(wrow + 64),  X0.y, a2[1]);
                a2[2] = fma2(*(const ull*)(wrow + 128), X1.x, a2[2]);
                a2[3] = fma2(*(const ull*)(wrow + 192), X1.y, a2[3]);
            }
            ull s01 = add2(a2[0], a2[1]);
            ull s23 = add2(a2[2], a2[3]);
            ull st  = add2(s01, s23);
            float lo, hi; upk2(st, lo, hi);
            float v = sm[OFF_B2 + lane] + lo + hi;
            sm[OFF_Y2 + lane * 8 + wq] = fmaxf(v, 0.0f);
        }
        __syncthreads();

        // ---- conv3 (i-split across 8 warps, scalar) + reduce + fc ----
        {
            float a3[8] = {0.f,0.f,0.f,0.f,0.f,0.f,0.f,0.f};
            #pragma unroll
            for (int ii = 0; ii < 4; ii++) {
                int i = wq * 4 + ii;
                float4 x0 = *(const float4*)&sm[OFF_Y2 + i * 8];
                float4 x1 = *(const float4*)&sm[OFF_Y2 + i * 8 + 4];
                a3[0] += sm[OFF_W3T + (i * 8 + 0) * 33 + lane] * x0.x;
                a3[1] += sm[OFF_W3T + (i * 8 + 1) * 33 + lane] * x0.y;
                a3[2] += sm[OFF_W3T + (i * 8 + 2) * 33 + lane] * x0.z;
                a3[3] += sm[OFF_W3T + (i * 8 + 3) * 33 + lane] * x0.w;
                a3[4] += sm[OFF_W3T + (i * 8 + 4) * 33 + lane] * x1.x;
                a3[5] += sm[OFF_W3T + (i * 8 + 5) * 33 + lane] * x1.y;
                a3[6] += sm[OFF_W3T + (i * 8 + 6) * 33 + lane] * x1.z;
                a3[7] += sm[OFF_W3T + (i * 8 + 7) * 33 + lane] * x1.w;
            }
            float pv = ((a3[0] + a3[1]) + (a3[2] + a3[3]))
                     + ((a3[4] + a3[5]) + (a3[6] + a3[7]));
            sm[OFF_RED + wq * 32 + lane] = pv;
        }
        __syncthreads();

        if (wq == 0) {
            float v = sm[OFF_B3 + lane];
            #pragma unroll
            for (int w = 0; w < 8; w++) v += sm[OFF_RED + w * 32 + lane];
            v = fmaxf(v, 0.0f) * sm[OFF_FCW + lane];
            #pragma unroll
            for (int off = 16; off > 0; off >>= 1)
                v += __shfl_down_sync(0xffffffffu, v, off);
            if (lane == 0)
                out[sample] = 1.0f / (1.0f + expf(-(v + fc_b)));
        }
        __syncthreads();   // protect A/B/C & RED before next iteration
    }
}

extern "C" void kernel_launch(void* const* d_in, const int* in_sizes, int n_in,
                              void* d_out, int out_size)
{
    const int*   gi  = (const int*)  d_in[0];
    const int*   gj  = (const int*)  d_in[1];
    const int*   gk  = (const int*)  d_in[2];
    const float* gA  = (const float*)d_in[3];
    const float* gB  = (const float*)d_in[4];
    const float* gC  = (const float*)d_in[5];
    const float* gW0 = (const float*)d_in[6];
    const float* gb0 = (const float*)d_in[7];
    const float* gW1 = (const float*)d_in[8];
    const float* gb1 = (const float*)d_in[9];
    const float* gW2 = (const float*)d_in[10];
    const float* gb2 = (const float*)d_in[11];
    const float* gW3 = (const float*)d_in[12];
    const float* gb3 = (const float*)d_in[13];
    const float* gfw = (const float*)d_in[14];
    const float* gfb = (const float*)d_in[15];
    float* out = (float*)d_out;

    int batch = in_sizes[0];

    int dev = 0, nsm = 148;
    cudaGetDevice(&dev);
    cudaDeviceGetAttribute(&nsm, cudaDevAttrMultiProcessorCount, dev);

    size_t smem = SMEM_FLOATS * sizeof(float);
    cudaFuncSetAttribute(ntc_fused_kernel,
                         cudaFuncAttributeMaxDynamicSharedMemorySize, (int)smem);

    ntc_fused_kernel<<<nsm, 256, smem>>>(gi, gj, gk, gA, gB, gC,
                                         gW0, gb0, gW1, gb1, gW2, gb2, gW3, gb3,
                                         gfw, gfb, out, batch, nsm);
}

// round 8
// speedup vs baseline: 1.4645x; 1.4645x over previous
#include <cuda_runtime.h>
#include <math.h>

typedef unsigned long long ull;

// ---- shared memory layout (float offsets; all 16B-aligned) ----
#define S_W1D  0          // W1 dup pair-major: [k=256][64]        = 16384
#define S_Y0   16384      // y0: [k=256][68] (64 cols used)        = 17408
#define S_Y1   33792      // y1: [k2=256][12] (8 cols used)        = 3072
#define S_RED  36864      // conv1 partials / conv2 partials       = 5120
#define S_Y2   41984      // y2: [o2*8+s3] flat                    = 256
#define S_RED3 42240      // conv3 partials: 8 x 32                = 256
#define S_B1   42496
#define S_B2   42528
#define S_B3   42560
#define S_FCW  42592
#define S_A    42624
#define S_B    42640
#define S_C    42656
#define S_TOT  42672      // ~170.7 KB -> 1 CTA/SM

__device__ __forceinline__ ull pk2(float lo, float hi) {
    ull r; asm("mov.b64 %0,{%1,%2};" : "=l"(r) : "f"(lo), "f"(hi)); return r;
}
__device__ __forceinline__ void upk2(ull v, float& lo, float& hi) {
    asm("mov.b64 {%0,%1},%2;" : "=f"(lo), "=f"(hi) : "l"(v));
}
__device__ __forceinline__ ull fma2(ull a, ull b, ull c) {
    ull d; asm("fma.rn.f32x2 %0,%1,%2,%3;" : "=l"(d) : "l"(a), "l"(b), "l"(c)); return d;
}
__device__ __forceinline__ ull add2(ull a, ull b) {
    ull d; asm("add.rn.f32x2 %0,%1,%2;" : "=l"(d) : "l"(a), "l"(b)); return d;
}
__device__ __forceinline__ ull mul2(ull a, ull b) {
    ull d; asm("mul.rn.f32x2 %0,%1,%2;" : "=l"(d) : "l"(a), "l"(b)); return d;
}

extern "C" __global__ void __launch_bounds__(256, 1)
ntc_fused_kernel(const int* __restrict__ gi, const int* __restrict__ gj,
                 const int* __restrict__ gk,
                 const float* __restrict__ gA, const float* __restrict__ gB,
                 const float* __restrict__ gC,
                 const float* __restrict__ gW0, const float* __restrict__ gb0,
                 const float* __restrict__ gW1, const float* __restrict__ gb1,
                 const float* __restrict__ gW2, const float* __restrict__ gb2,
                 const float* __restrict__ gW3, const float* __restrict__ gb3,
                 const float* __restrict__ gfcw, const float* __restrict__ gfcb,
                 float* __restrict__ out, int batch, int gridSize)
{
    extern __shared__ float sm[];
    const int tid  = threadIdx.x;
    const int lane = tid & 31;
    const int wq   = tid >> 5;

    // ---- one-time staging: W1 duplicated pair-major ----
    for (int idx = tid; idx < 32 * 256; idx += 256) {
        int o = idx >> 8, k = idx & 255;
        float w = gW1[idx];
        sm[S_W1D + k * 64 + o * 2]     = w;
        sm[S_W1D + k * 64 + o * 2 + 1] = w;
    }
    if (tid < 32) {
        sm[S_B1 + tid]  = gb1[tid];
        sm[S_B2 + tid]  = gb2[tid];
        sm[S_B3 + tid]  = gb3[tid];
        sm[S_FCW + tid] = gfcw[tid];
    }
    const float fc_b = gfcb[0];

    // ---- register-resident weights ----
    const int f0 = tid >> 3, s0 = tid & 7;            // conv0: thread = y0 row
    const int sa = s0 >> 2, sb = (s0 >> 1) & 1, sc = s0 & 1;
    ull W0d[8];
    #pragma unroll
    for (int t = 0; t < 8; t++) { float w = gW0[f0 * 8 + t]; W0d[t] = pk2(w, w); }
    const float b0f = gb0[f0];
    float w2r[32];                                    // conv2: warp = k2-slice, lane = o2
    #pragma unroll
    for (int t = 0; t < 32; t++) w2r[t] = gW2[lane * 256 + wq * 32 + t];
    float w3r[32];                                    // conv3: warp = o2-slice, lane = o3
    #pragma unroll
    for (int t = 0; t < 32; t++) w3r[t] = gW3[lane * 256 + wq * 32 + t];

    // conv1 roles: 2 k-halves x 4 tile-warps; warp tile 16o x 32p; thread 4o x 4p
    const int half = wq >> 2, tw = wq & 3;
    const int o0 = (tw >> 1) * 16 + (lane >> 3) * 4;
    const int p0 = (tw & 1) * 32 + (lane & 7) * 4;

    __syncthreads();

    for (int sample = blockIdx.x; sample < batch; sample += gridSize) {
        if (tid < 48) {
            int which = tid >> 4, t = tid & 15;
            if (which == 0)       sm[S_A + t] = gA[gi[sample] * 16 + t];
            else if (which == 1)  sm[S_B + t] = gB[gj[sample] * 16 + t];
            else                  sm[S_C + t] = gC[gk[sample] * 16 + t];
        }
        __syncthreads();                                     // B1

        // ======== conv0: thread computes y0 row k=tid (64 positions, (q2,s2) order) ========
        {
            ull cp[2][2];                                    // packed over w1-pairs (2j,2j+1)
            #pragma unroll
            for (int tc = 0; tc < 2; tc++)
                #pragma unroll
                for (int j = 0; j < 2; j++)
                    cp[tc][j] = pk2(sm[S_C + 8 * j + 2 * sc + tc],
                                    sm[S_C + 8 * j + 4 + 2 * sc + tc]);
            ull T2[2][4][2];
            #pragma unroll
            for (int ta = 0; ta < 2; ta++) {
                ull T1[2][2];
                #pragma unroll
                for (int tb = 0; tb < 2; tb++)
                    #pragma unroll
                    for (int j = 0; j < 2; j++)
                        T1[tb][j] = fma2(W0d[ta * 4 + tb * 2 + 1], cp[1][j],
                                    mul2(W0d[ta * 4 + tb * 2 + 0], cp[0][j]));
                #pragma unroll
                for (int h1 = 0; h1 < 4; h1++) {
                    float bb0 = sm[S_B + 4 * h1 + 2 * sb];
                    float bb1 = sm[S_B + 4 * h1 + 2 * sb + 1];
                    #pragma unroll
                    for (int j = 0; j < 2; j++)
                        T2[ta][h1][j] = fma2(pk2(bb1, bb1), T1[1][j],
                                        mul2(pk2(bb0, bb0), T1[0][j]));
                }
            }
            const ull b0d = pk2(b0f, b0f);
            float* yrow = sm + S_Y0 + tid * 68;
            #pragma unroll
            for (int d1 = 0; d1 < 4; d1++) {
                float aa0 = sm[S_A + 4 * d1 + 2 * sa];
                float aa1 = sm[S_A + 4 * d1 + 2 * sa + 1];
                ull ad0 = pk2(aa0, aa0), ad1 = pk2(aa1, aa1);
                int s2b = (d1 & 1) * 4;
                #pragma unroll
                for (int hh = 0; hh < 2; hh++)
                    #pragma unroll
                    for (int j = 0; j < 2; j++) {
                        ull Ta = fma2(ad0, T2[0][2 * hh][j],
                                 fma2(ad1, T2[1][2 * hh][j], b0d));
                        ull Tb = fma2(ad0, T2[0][2 * hh + 1][j],
                                 fma2(ad1, T2[1][2 * hh + 1][j], b0d));
                        float v0, v1, v2, v3;
                        upk2(Ta, v0, v1); upk2(Tb, v2, v3);
                        int q2 = (d1 >> 1) * 4 + hh * 2 + j;
                        *(float4*)(yrow + q2 * 8 + s2b) =
                            make_float4(fmaxf(v0, 0.f), fmaxf(v1, 0.f),
                                        fmaxf(v2, 0.f), fmaxf(v3, 0.f));
                    }
            }
        }
        __syncthreads();                                     // B2

        // ======== conv1: GEMM 32o x 64p x 256k, k-halved across warp groups ========
        ull acc[4][2] = {{0,0},{0,0},{0,0},{0,0}};
        {
            const float* xb = sm + S_Y0 + half * (128 * 68) + p0;
            const float* wb = sm + S_W1D + half * (128 * 64) + o0 * 2;
            #pragma unroll 8
            for (int kk = 0; kk < 128; kk++) {
                ulonglong2 X  = *(const ulonglong2*)(xb + kk * 68);
                ulonglong2 Wa = *(const ulonglong2*)(wb + kk * 64);
                ulonglong2 Wb = *(const ulonglong2*)(wb + kk * 64 + 4);
                acc[0][0] = fma2(Wa.x, X.x, acc[0][0]);
                acc[0][1] = fma2(Wa.x, X.y, acc[0][1]);
                acc[1][0] = fma2(Wa.y, X.x, acc[1][0]);
                acc[1][1] = fma2(Wa.y, X.y, acc[1][1]);
                acc[2][0] = fma2(Wb.x, X.x, acc[2][0]);
                acc[2][1] = fma2(Wb.x, X.y, acc[2][1]);
                acc[3][0] = fma2(Wb.y, X.x, acc[3][0]);
                acc[3][1] = fma2(Wb.y, X.y, acc[3][1]);
            }
        }
        if (half) {
            float* r = sm + S_RED + (tw * 32 + lane) * 20;
            #pragma unroll
            for (int c = 0; c < 4; c++) {
                ulonglong2 v; v.x = acc[c][0]; v.y = acc[c][1];
                *(ulonglong2*)(r + c * 4) = v;
            }
        }
        __syncthreads();                                     // B3
        if (!half) {
            const float* r = sm + S_RED + (tw * 32 + lane) * 20;
            #pragma unroll
            for (int c = 0; c < 4; c++) {
                ulonglong2 P = *(const ulonglong2*)(r + c * 4);
                acc[c][0] = add2(acc[c][0], P.x);
                acc[c][1] = add2(acc[c][1], P.y);
            }
            #pragma unroll
            for (int o = 0; o < 4; o++) {
                float bb = sm[S_B1 + o0 + o];
                ull bd = pk2(bb, bb);
                #pragma unroll
                for (int pp = 0; pp < 2; pp++) {
                    float lo, hi; upk2(add2(acc[o][pp], bd), lo, hi);
                    int pa = p0 + pp * 2, pb = pa + 1;
                    sm[S_Y1 + ((o0 + o) * 8 + (pa & 7)) * 12 + (pa >> 3)] = fmaxf(lo, 0.f);
                    sm[S_Y1 + ((o0 + o) * 8 + (pb & 7)) * 12 + (pb >> 3)] = fmaxf(hi, 0.f);
                }
            }
        }
        __syncthreads();                                     // B4

        // ======== conv2: register weights, warp = k2-slice [wq*32, wq*32+32), lane = o2 ========
        {
            ull a2[4] = {0,0,0,0};
            const float* yb = sm + S_Y1 + wq * 32 * 12;
            #pragma unroll
            for (int t = 0; t < 32; t++) {
                ulonglong2 X0 = *(const ulonglong2*)(yb + t * 12);
                ulonglong2 X1 = *(const ulonglong2*)(yb + t * 12 + 4);
                ull wd = pk2(w2r[t], w2r[t]);
                a2[0] = fma2(wd, X0.x, a2[0]);
                a2[1] = fma2(wd, X0.y, a2[1]);
                a2[2] = fma2(wd, X1.x, a2[2]);
                a2[3] = fma2(wd, X1.y, a2[3]);
            }
            // store partials: red[w][o2][q2], row stride 9 (conflict-free)
            float* r = sm + S_RED + wq * 288 + lane * 9;
            #pragma unroll
            for (int c = 0; c < 4; c++) {
                float lo, hi; upk2(a2[c], lo, hi);
                r[c * 2] = lo; r[c * 2 + 1] = hi;
            }
        }
        __syncthreads();                                     // B5
        {
            // thread tid owns output (o2 = tid>>3, s3 = tid&7)
            float v = sm[S_B2 + (tid >> 3)];
            const float* r = sm + S_RED + (tid >> 3) * 9 + (tid & 7);
            #pragma unroll
            for (int w = 0; w < 8; w++) v += r[w * 288];
            sm[S_Y2 + tid] = fmaxf(v, 0.f);                  // y2[o2*8+s3], coalesced
        }
        __syncthreads();                                     // B6

        // ======== conv3: warp = k3-slice (o2 in [wq*4,wq*4+4)), lane = o3 ========
        {
            float a3 = 0.f;
            #pragma unroll
            for (int ii = 0; ii < 4; ii++) {
                float4 x0 = *(const float4*)&sm[S_Y2 + (wq * 4 + ii) * 8];
                float4 x1 = *(const float4*)&sm[S_Y2 + (wq * 4 + ii) * 8 + 4];
                a3 += w3r[ii * 8 + 0] * x0.x + w3r[ii * 8 + 1] * x0.y
                    + w3r[ii * 8 + 2] * x0.z + w3r[ii * 8 + 3] * x0.w
                    + w3r[ii * 8 + 4] * x1.x + w3r[ii * 8 + 5] * x1.y
                    + w3r[ii * 8 + 6] * x1.z + w3r[ii * 8 + 7] * x1.w;
            }
            sm[S_RED3 + wq * 32 + lane] = a3;
        }
        __syncthreads();                                     // B7

        if (wq == 0) {
            float v = sm[S_B3 + lane];
            #pragma unroll
            for (int w = 0; w < 8; w++) v += sm[S_RED3 + w * 32 + lane];
            v = fmaxf(v, 0.f) * sm[S_FCW + lane];
            #pragma unroll
            for (int off = 16; off > 0; off >>= 1)
                v += __shfl_down_sync(0xffffffffu, v, off);
            if (lane == 0)
                out[sample] = 1.0f / (1.0f + expf(-(v + fc_b)));
        }
        __syncthreads();                                     // B8 (protect RED3/Y2 reuse)
    }
}

extern "C" void kernel_launch(void* const* d_in, const int* in_sizes, int n_in,
                              void* d_out, int out_size)
{
    const int*   gi  = (const int*)  d_in[0];
    const int*   gj  = (const int*)  d_in[1];
    const int*   gk  = (const int*)  d_in[2];
    const float* gA  = (const float*)d_in[3];
    const float* gB  = (const float*)d_in[4];
    const float* gC  = (const float*)d_in[5];
    const float* gW0 = (const float*)d_in[6];
    const float* gb0 = (const float*)d_in[7];
    const float* gW1 = (const float*)d_in[8];
    const float* gb1 = (const float*)d_in[9];
    const float* gW2 = (const float*)d_in[10];
    const float* gb2 = (const float*)d_in[11];
    const float* gW3 = (const float*)d_in[12];
    const float* gb3 = (const float*)d_in[13];
    const float* gfw = (const float*)d_in[14];
    const float* gfb = (const float*)d_in[15];
    float* out = (float*)d_out;

    int batch = in_sizes[0];
    int dev = 0, nsm = 148;
    cudaGetDevice(&dev);
    cudaDeviceGetAttribute(&nsm, cudaDevAttrMultiProcessorCount, dev);

    size_t smem = S_TOT * sizeof(float);
    cudaFuncSetAttribute(ntc_fused_kernel,
                         cudaFuncAttributeMaxDynamicSharedMemorySize, (int)smem);

    ntc_fused_kernel<<<nsm, 256, smem>>>(gi, gj, gk, gA, gB, gC,
                                         gW0, gb0, gW1, gb1, gW2, gb2, gW3, gb3,
                                         gfw, gfb, out, batch, nsm);
}